// round 10
// baseline (speedup 1.0000x reference)
#include <cuda_runtime.h>
#include <cstdint>

#define BATCH 64
#define TLEN  512
#define D     1024

// ---------------- scratch (device globals: no allocations allowed) ----------------
__device__ float g_ext[(size_t)TLEN * BATCH * D];   // 128 MB, layout [t][b][o]
__device__ float g_stateA[BATCH * D];
__device__ float g_stateB[BATCH * D];
__device__ unsigned g_bars[4 * 32];                  // per-m-group barrier counters

typedef unsigned long long ULL;

// ---------------- packed f32x2 helpers (sm_103a FFMA2 path) ----------------
static __device__ __forceinline__ ULL pack_dup(float w) {
    ULL r;
    asm("mov.b64 %0, {%1, %1};" : "=l"(r) : "f"(w));
    return r;
}
static __device__ __forceinline__ void fma2(ULL& d, ULL a, ULL b) {
    asm("fma.rn.f32x2 %0, %1, %2, %0;" : "+l"(d) : "l"(a), "l"(b));
}
static __device__ __forceinline__ void unpack2(ULL v, float& lo, float& hi) {
    asm("mov.b64 {%0, %1}, %2;" : "=f"(lo), "=f"(hi) : "l"(v));
}

// ---------------- trivial zero kernels ----------------
__global__ void zero4_kernel(float4* __restrict__ p, int n4) {
    int i = blockIdx.x * blockDim.x + threadIdx.x;
    if (i < n4) p[i] = make_float4(0.f, 0.f, 0.f, 0.f);
}
__global__ void zero_state_kernel() {
    int i = blockIdx.x * blockDim.x + threadIdx.x;
    if (i < BATCH * D) g_stateA[i] = 0.f;
    if (i < 4 * 32) g_bars[i] = 0u;
}

// ---------------- Phase A: ext[t][b][o] = sum_k x[m][k] * W_in[o][k], m=b*512+t --------
// m-pair-packed FFMA2 GEMM. BM=256, BN=64, BK=16, 256 threads, 16m x 4n per thread
// (32 ULL acc = 64 regs). Transposed smem tiles, double-buffered, ONE sync per tile.
// Per kk: 8 broadcast LDS.64 (A) + 1 LDS.128 (B) + 4 MOV + 32 FFMA2.
#define BM 256
#define BN 64
#define BK 16
#define AROWS 260                        // floats per As k-row (256 + 4 pad; 2-way max)
#define BROWS 68                         // floats per Bs k-row (64 + 4 pad)
#define A_STG (BK * AROWS)               // 4160 floats
#define B_STG (BK * BROWS)               // 1088 floats
#define EXT_SMEM (2 * (A_STG + B_STG) * 4)   // 41984 B

__global__ __launch_bounds__(256, 2) void ext_gemm_kernel(const float* __restrict__ X,
                                                          const float* __restrict__ Win) {
    extern __shared__ float esm[];
    float* As = esm;                     // 2 stages: As[k][m]
    float* Bs = esm + 2 * A_STG;         // 2 stages: Bs[k][n]

    const int tid = threadIdx.x;
    const int Mb = blockIdx.y * BM;
    const int Nb = blockIdx.x * BN;
    const int ty = tid >> 4, tx = tid & 15;
    const int m0 = ty * 16;              // 16 m rows (8 pairs)
    const int n0 = tx * 4;               // 4 n cols

    ULL acc[8][4];
#pragma unroll
    for (int i = 0; i < 8; ++i)
#pragma unroll
        for (int j = 0; j < 4; ++j) acc[i][j] = 0ULL;

    // loaders: A row ar+g*64 (g=0..3), float4 col aq; B row bn, float4 col bq
    const int ar = tid >> 2, aq = tid & 3;
    const int bn = tid >> 2, bq = tid & 3;
    const float* aSrc = X + (size_t)(Mb + ar) * D + aq * 4;
    const float* bSrc = Win + (size_t)(Nb + bn) * D + bq * 4;

    float4 ra[4], rb;
#pragma unroll
    for (int g = 0; g < 4; ++g)
        ra[g] = *(const float4*)(aSrc + (size_t)g * 64 * D);
    rb = *(const float4*)(bSrc);
    {
#pragma unroll
        for (int g = 0; g < 4; ++g) {
            const int m = ar + g * 64;
            As[(aq * 4 + 0) * AROWS + m] = ra[g].x;
            As[(aq * 4 + 1) * AROWS + m] = ra[g].y;
            As[(aq * 4 + 2) * AROWS + m] = ra[g].z;
            As[(aq * 4 + 3) * AROWS + m] = ra[g].w;
        }
        Bs[(bq * 4 + 0) * BROWS + bn] = rb.x;
        Bs[(bq * 4 + 1) * BROWS + bn] = rb.y;
        Bs[(bq * 4 + 2) * BROWS + bn] = rb.z;
        Bs[(bq * 4 + 3) * BROWS + bn] = rb.w;
    }
    __syncthreads();

    for (int kt = 0; kt < D / BK; ++kt) {
        const int s = kt & 1;
        const float* Ac = As + s * A_STG + m0;
        const float* Bc = Bs + s * B_STG + n0;

        // fetch next tile into registers (latency hidden by compute below)
        if (kt < D / BK - 1) {
            const int k0 = (kt + 1) * BK;
#pragma unroll
            for (int g = 0; g < 4; ++g)
                ra[g] = *(const float4*)(aSrc + (size_t)g * 64 * D + k0);
            rb = *(const float4*)(bSrc + k0);
        }

        // compute this tile
#pragma unroll
        for (int kk = 0; kk < BK; ++kk) {
            float4 bv = *(const float4*)(Bc + kk * BROWS);
            ULL b0 = pack_dup(bv.x);
            ULL b1 = pack_dup(bv.y);
            ULL b2 = pack_dup(bv.z);
            ULL b3 = pack_dup(bv.w);
            const float* arow = Ac + kk * AROWS;
#pragma unroll
            for (int i = 0; i < 8; ++i) {
                ULL a = *(const ULL*)(arow + 2 * i);
                fma2(acc[i][0], a, b0);
                fma2(acc[i][1], a, b1);
                fma2(acc[i][2], a, b2);
                fma2(acc[i][3], a, b3);
            }
        }

        // stage next tile
        if (kt < D / BK - 1) {
            float* An = As + (s ^ 1) * A_STG;
            float* Bn = Bs + (s ^ 1) * B_STG;
#pragma unroll
            for (int g = 0; g < 4; ++g) {
                const int m = ar + g * 64;
                An[(aq * 4 + 0) * AROWS + m] = ra[g].x;
                An[(aq * 4 + 1) * AROWS + m] = ra[g].y;
                An[(aq * 4 + 2) * AROWS + m] = ra[g].z;
                An[(aq * 4 + 3) * AROWS + m] = ra[g].w;
            }
            Bn[(bq * 4 + 0) * BROWS + bn] = rb.x;
            Bn[(bq * 4 + 1) * BROWS + bn] = rb.y;
            Bn[(bq * 4 + 2) * BROWS + bn] = rb.z;
            Bn[(bq * 4 + 3) * BROWS + bn] = rb.w;
        }
        __syncthreads();
    }

    // ---- epilogue: unpack m-pairs, store to g_ext [t][b][o] ----
    // BM=256 aligned: all rows in this tile share b-block boundaries cleanly.
#pragma unroll
    for (int i = 0; i < 8; ++i) {
        float lo[4], hi[4];
#pragma unroll
        for (int j = 0; j < 4; ++j) unpack2(acc[i][j], lo[j], hi[j]);
        const int m = Mb + m0 + 2 * i;
        const int b0i = m >> 9, t0i = m & 511;
        const int b1i = (m + 1) >> 9, t1i = (m + 1) & 511;
        *(float4*)&g_ext[((size_t)t0i * BATCH + b0i) * D + Nb + n0] = make_float4(lo[0], lo[1], lo[2], lo[3]);
        *(float4*)&g_ext[((size_t)t1i * BATCH + b1i) * D + Nb + n0] = make_float4(hi[0], hi[1], hi[2], hi[3]);
    }
}

// ---------------- Phase B: persistent recurrence, W_rec in registers ----------------
// (unchanged from round 7 — measured at its fma floor)
#define NTILE 32
#define MTILE 16
#define SSTR  1028
#define PERS_SMEM ((MTILE * SSTR + 8 * 512) * 4)   // 82176 B

__global__ __launch_bounds__(256, 1) void rnn_persistent(const float* __restrict__ Wr) {
    extern __shared__ float sm[];
    float* sTile = sm;                   // [16][SSTR]
    float* red   = sm + MTILE * SSTR;    // [8 kgroups][16 m * 32 n]

    const int tid = threadIdx.x;
    const int w   = tid >> 5;            // warp = 128-wide k-slice (0..7)
    const int l   = tid & 31;            // lane = n
    const int Nb  = blockIdx.x * NTILE;
    const int Mb  = blockIdx.y * MTILE;
    unsigned* bar = &g_bars[blockIdx.y * 32];

    const int r  = tid >> 4;             // staging row 0..15
    const int c0 = tid & 15;             // float4 column base

    ULL w2[64];
    {
        const float* wp = Wr + (size_t)(Nb + l) * D + w * 128;
#pragma unroll
        for (int j = 0; j < 32; ++j) {
            ulonglong2 v = *(const ulonglong2*)(wp + 4 * j);
            w2[2 * j]     = v.x;
            w2[2 * j + 1] = v.y;
        }
    }

    {
        const float4* esrc = (const float4*)(g_ext + (size_t)(Mb + r) * D);
        float* sdst = sTile + r * SSTR;
#pragma unroll
        for (int j = 0; j < 16; ++j) {
            const int q = c0 + j * 16;
            *(float4*)(sdst + q * 4) = __ldg(esrc + q);
        }
    }
    __syncthreads();

    for (int t = 0; t < TLEN; ++t) {
        float* sout = (t & 1) ? g_stateA : g_stateB;

        if (t > 0) {
            const float* sin = (t & 1) ? g_stateB : g_stateA;
            if (tid == 0) {
                const unsigned target = 32u * (unsigned)t;
                unsigned v;
                do {
                    asm volatile("ld.acquire.gpu.u32 %0, [%1];" : "=r"(v) : "l"(bar));
                } while (v < target);
            }
            __syncthreads();

            const float4* ssrc = (const float4*)(sin + (size_t)(Mb + r) * D);
            float* sdst = sTile + r * SSTR;
#pragma unroll
            for (int j = 0; j < 16; j += 2) {
                const int q0 = c0 + j * 16;
                const int q1 = c0 + (j + 1) * 16;
                float4 a0 = __ldcg(ssrc + q0);
                float4 a1 = __ldcg(ssrc + q1);
                float4 b0 = *(const float4*)(sdst + q0 * 4);
                float4 b1 = *(const float4*)(sdst + q1 * 4);
                *(float4*)(sdst + q0 * 4) = make_float4(a0.x + b0.x, a0.y + b0.y, a0.z + b0.z, a0.w + b0.w);
                *(float4*)(sdst + q1 * 4) = make_float4(a1.x + b1.x, a1.y + b1.y, a1.z + b1.z, a1.w + b1.w);
            }
            __syncthreads();
        }

        ULL acc[16];
#pragma unroll
        for (int i = 0; i < 16; ++i) acc[i] = 0ULL;

        const float* sb = sTile + w * 128;
#pragma unroll
        for (int m = 0; m < 16; ++m) {
            const ulonglong2* srow = (const ulonglong2*)(sb + (size_t)m * SSTR);
#pragma unroll
            for (int j = 0; j < 32; ++j) {
                ulonglong2 sv = srow[j];
                fma2(acc[m], sv.x, w2[2 * j]);
                fma2(acc[m], sv.y, w2[2 * j + 1]);
            }
        }

#pragma unroll
        for (int m = 0; m < 16; ++m) {
            float lo, hi;
            unpack2(acc[m], lo, hi);
            red[w * 512 + m * 32 + l] = lo + hi;
        }
        __syncthreads();

#pragma unroll
        for (int rep = 0; rep < 2; ++rep) {
            const int idx = tid + rep * 256;
            const int rm = idx >> 5, rn = idx & 31;
            float s0 = 0.f, s1 = 0.f;
#pragma unroll
            for (int g = 0; g < 8; g += 2) {
                s0 += red[g * 512 + idx];
                s1 += red[(g + 1) * 512 + idx];
            }
            __stcg(&sout[(size_t)(Mb + rm) * D + Nb + rn], fmaxf(s0 + s1, 0.f));
        }
        __syncthreads();

        if (tid == 0) {
            __threadfence();
            atomicAdd(bar, 1u);
        }
        if (t + 1 < TLEN) {
            const float4* esrc = (const float4*)(g_ext + (size_t)(t + 1) * (BATCH * D) + (size_t)(Mb + r) * D);
            float* sdst = sTile + r * SSTR;
#pragma unroll
            for (int j = 0; j < 16; ++j) {
                const int q = c0 + j * 16;
                *(float4*)(sdst + q * 4) = __ldg(esrc + q);
            }
        }
    }
}

// ---------------- final: out[:,0,:] = final state ----------------
__global__ void final_copy_kernel(float* __restrict__ out) {
    const int i = blockIdx.x * blockDim.x + threadIdx.x;   // < 65536
    const int b = i >> 10, o = i & 1023;
    out[(size_t)b * (TLEN * D) + o] = g_stateA[i];
}

// ---------------- launch ----------------
extern "C" void kernel_launch(void* const* d_in, const int* in_sizes, int n_in,
                              void* d_out, int out_size) {
    const float* x     = (const float*)d_in[0];
    const float* W_in  = (const float*)d_in[1];
    const float* W_rec = (const float*)d_in[2];
    float* out = (float*)d_out;

    cudaFuncSetAttribute(rnn_persistent, cudaFuncAttributeMaxDynamicSharedMemorySize, PERS_SMEM);
    cudaFuncSetAttribute(ext_gemm_kernel, cudaFuncAttributeMaxDynamicSharedMemorySize, EXT_SMEM);

    // zero output (poisoned by harness), initial state, barrier counters
    zero4_kernel<<<(BATCH * TLEN * D / 4 + 255) / 256, 256>>>((float4*)out, BATCH * TLEN * D / 4);
    zero_state_kernel<<<(BATCH * D + 255) / 256, 256>>>();

    // Phase A: input projections for all timesteps (ext layout [t][b][o])
    ext_gemm_kernel<<<dim3(D / BN, (BATCH * TLEN) / BM), 256, EXT_SMEM>>>(x, W_in);

    // Phase B: full recurrence in one persistent kernel
    rnn_persistent<<<dim3(D / NTILE, BATCH / MTILE), 256, PERS_SMEM>>>(W_rec);

    // write final state into out[:,0,:]
    final_copy_kernel<<<(BATCH * D) / 256, 256>>>(out);
}

// round 11
// speedup vs baseline: 1.0957x; 1.0957x over previous
#include <cuda_runtime.h>
#include <cstdint>

#define BATCH 64
#define TLEN  512
#define D     1024

// ---------------- scratch (device globals: no allocations allowed) ----------------
__device__ float g_ext[(size_t)TLEN * BATCH * D];   // 128 MB, layout [t][b][o]
__device__ float g_sbuf[2][BATCH * D];              // ping-pong: state + ext[t] combined
__device__ unsigned g_bars[4 * 32];                  // per-m-group barrier counters

typedef unsigned long long ULL;

// ---------------- packed f32x2 helpers (sm_103a FFMA2 path) ----------------
static __device__ __forceinline__ ULL pack_dup(float w) {
    ULL r;
    asm("mov.b64 %0, {%1, %1};" : "=l"(r) : "f"(w));
    return r;
}
static __device__ __forceinline__ void fma2(ULL& d, ULL a, ULL b) {
    asm("fma.rn.f32x2 %0, %1, %2, %0;" : "+l"(d) : "l"(a), "l"(b));
}
static __device__ __forceinline__ void unpack2(ULL v, float& lo, float& hi) {
    asm("mov.b64 {%0, %1}, %2;" : "=f"(lo), "=f"(hi) : "l"(v));
}
static __device__ __forceinline__ uint32_t smem_u32(const void* p) {
    uint32_t a;
    asm("{ .reg .u64 t; cvta.to.shared.u64 t, %1; cvt.u32.u64 %0, t; }" : "=r"(a) : "l"(p));
    return a;
}

// ---------------- trivial zero kernels ----------------
__global__ void zero4_kernel(float4* __restrict__ p, int n4) {
    int i = blockIdx.x * blockDim.x + threadIdx.x;
    if (i < n4) p[i] = make_float4(0.f, 0.f, 0.f, 0.f);
}
__global__ void zero_misc_kernel() {
    int i = blockIdx.x * blockDim.x + threadIdx.x;
    if (i < 4 * 32) g_bars[i] = 0u;
}

// ---------------- Phase A: ext[t][b][o] = sum_k x[m][k] * W_in[o][k], m=b*512+t --------
// (round-7 version: double-buffered, 2 CTAs/SM)
#define BM 128
#define BN 64
#define BK 32
#define PADA 134
#define PADB 68
#define ASTRIDE (BK * PADA)
#define BSTRIDE (BK * PADB)
#define EXT_SMEM ((2 * ASTRIDE + 2 * BSTRIDE) * 4)   // 51712 B

__global__ __launch_bounds__(256, 2) void ext_gemm_kernel(const float* __restrict__ X,
                                                          const float* __restrict__ Win) {
    extern __shared__ float esm[];
    float* As = esm;
    float* Bs = esm + 2 * ASTRIDE;

    const int tid = threadIdx.x;
    const int Mb = blockIdx.y * BM;
    const int Nb = blockIdx.x * BN;
    const int ty = tid >> 4, tx = tid & 15;
    const int m0 = ty * 8, n0 = tx * 4;

    ULL acc[4][4];
#pragma unroll
    for (int i = 0; i < 4; ++i)
#pragma unroll
        for (int j = 0; j < 4; ++j) acc[i][j] = 0ULL;

    const int ar = tid >> 3, ac = tid & 7;
    const int br = tid >> 2, bc = tid & 3;

    float4 ra[4], rb[2];
#pragma unroll
    for (int g = 0; g < 4; ++g)
        ra[g] = *(const float4*)&X[(size_t)(Mb + ar + g * 32) * D + ac * 4];
#pragma unroll
    for (int g = 0; g < 2; ++g)
        rb[g] = *(const float4*)&Win[(size_t)(Nb + br) * D + (bc + g * 4) * 4];
    {
#pragma unroll
        for (int g = 0; g < 4; ++g) {
            const int m = ar + g * 32;
            As[(ac * 4 + 0) * PADA + m] = ra[g].x;
            As[(ac * 4 + 1) * PADA + m] = ra[g].y;
            As[(ac * 4 + 2) * PADA + m] = ra[g].z;
            As[(ac * 4 + 3) * PADA + m] = ra[g].w;
        }
#pragma unroll
        for (int g = 0; g < 2; ++g) {
            const int cc = bc + g * 4;
            Bs[(cc * 4 + 0) * PADB + br] = rb[g].x;
            Bs[(cc * 4 + 1) * PADB + br] = rb[g].y;
            Bs[(cc * 4 + 2) * PADB + br] = rb[g].z;
            Bs[(cc * 4 + 3) * PADB + br] = rb[g].w;
        }
    }
    __syncthreads();

    for (int kt = 0; kt < D / BK; ++kt) {
        const int s = kt & 1;
        const float* Ac = As + s * ASTRIDE;
        const float* Bc = Bs + s * BSTRIDE;

        if (kt < D / BK - 1) {
            const int k0 = (kt + 1) * BK;
#pragma unroll
            for (int g = 0; g < 4; ++g)
                ra[g] = *(const float4*)&X[(size_t)(Mb + ar + g * 32) * D + k0 + ac * 4];
#pragma unroll
            for (int g = 0; g < 2; ++g)
                rb[g] = *(const float4*)&Win[(size_t)(Nb + br) * D + k0 + (bc + g * 4) * 4];
        }

#pragma unroll
        for (int kk = 0; kk < BK; ++kk) {
            const float* asr = &Ac[kk * PADA + m0];
            ULL a0 = *(const ULL*)(asr + 0);
            ULL a1 = *(const ULL*)(asr + 2);
            ULL a2 = *(const ULL*)(asr + 4);
            ULL a3 = *(const ULL*)(asr + 6);
            float4 bv = *(const float4*)&Bc[kk * PADB + n0];
            ULL b0 = pack_dup(bv.x);
            ULL b1 = pack_dup(bv.y);
            ULL b2 = pack_dup(bv.z);
            ULL b3 = pack_dup(bv.w);
            fma2(acc[0][0], a0, b0); fma2(acc[0][1], a0, b1); fma2(acc[0][2], a0, b2); fma2(acc[0][3], a0, b3);
            fma2(acc[1][0], a1, b0); fma2(acc[1][1], a1, b1); fma2(acc[1][2], a1, b2); fma2(acc[1][3], a1, b3);
            fma2(acc[2][0], a2, b0); fma2(acc[2][1], a2, b1); fma2(acc[2][2], a2, b2); fma2(acc[2][3], a2, b3);
            fma2(acc[3][0], a3, b0); fma2(acc[3][1], a3, b1); fma2(acc[3][2], a3, b2); fma2(acc[3][3], a3, b3);
        }

        if (kt < D / BK - 1) {
            float* An = As + (s ^ 1) * ASTRIDE;
            float* Bn = Bs + (s ^ 1) * BSTRIDE;
#pragma unroll
            for (int g = 0; g < 4; ++g) {
                const int m = ar + g * 32;
                An[(ac * 4 + 0) * PADA + m] = ra[g].x;
                An[(ac * 4 + 1) * PADA + m] = ra[g].y;
                An[(ac * 4 + 2) * PADA + m] = ra[g].z;
                An[(ac * 4 + 3) * PADA + m] = ra[g].w;
            }
#pragma unroll
            for (int g = 0; g < 2; ++g) {
                const int cc = bc + g * 4;
                Bn[(cc * 4 + 0) * PADB + br] = rb[g].x;
                Bn[(cc * 4 + 1) * PADB + br] = rb[g].y;
                Bn[(cc * 4 + 2) * PADB + br] = rb[g].z;
                Bn[(cc * 4 + 3) * PADB + br] = rb[g].w;
            }
        }
        __syncthreads();
    }

#pragma unroll
    for (int i = 0; i < 4; ++i) {
        float lo[4], hi[4];
#pragma unroll
        for (int j = 0; j < 4; ++j) unpack2(acc[i][j], lo[j], hi[j]);
        const int m = Mb + m0 + 2 * i;
        const int b0i = m >> 9, t0i = m & 511;
        const int b1i = (m + 1) >> 9, t1i = (m + 1) & 511;
        *(float4*)&g_ext[((size_t)t0i * BATCH + b0i) * D + Nb + n0] = make_float4(lo[0], lo[1], lo[2], lo[3]);
        *(float4*)&g_ext[((size_t)t1i * BATCH + b1i) * D + Nb + n0] = make_float4(hi[0], hi[1], hi[2], hi[3]);
    }
}

// ---------------- Phase B: persistent recurrence ----------------
// 256 threads, W_rec fragment in registers (R7 compute loop).
// Staging: ONE cp.async.bulk (64KB, contiguous rows in g_sbuf / g_ext[0]) per step
// -> zero per-thread LDG dispatch. Epilogue writes s_next = relu(sum) + ext[t+1]
// directly (combined buffer), eliminating the add-pass.
#define NTILE 32
#define MTILE 16
#define S_FLOATS (MTILE * D)                 // 16384 floats = 64KB
#define RED_FLOATS (8 * 512)                 // 16KB
#define MBAR_OFF ((S_FLOATS + RED_FLOATS) * 4)
#define PERS_SMEM (MBAR_OFF + 16)
#define TILE_BYTES (MTILE * D * 4)           // 65536

__global__ __launch_bounds__(256, 1) void rnn_persistent(const float* __restrict__ Wr) {
    extern __shared__ float sm[];
    float* sTile = sm;                        // [16][1024]
    float* red   = sm + S_FLOATS;             // [8][512]

    const int tid = threadIdx.x;
    const int w   = tid >> 5;                 // warp = 128-wide k-slice (0..7)
    const int l   = tid & 31;                 // lane = n
    const int Nb  = blockIdx.x * NTILE;
    const int Mb  = blockIdx.y * MTILE;
    unsigned* bar = &g_bars[blockIdx.y * 32];

    const uint32_t sTile_a = smem_u32(sTile);
    const uint32_t mbar_a  = smem_u32((char*)sm + MBAR_OFF);

    // output mapping for reduce/epilogue: idx = tid, tid+256
    const int rm0 = tid >> 5,          rn0 = tid & 31;
    const int rm1 = (tid + 256) >> 5,  rn1 = tid & 31;

    // ---- W fragment -> registers (128 floats, held for all 512 steps) ----
    ULL w2[64];
    {
        const float* wp = Wr + (size_t)(Nb + l) * D + w * 128;
#pragma unroll
        for (int j = 0; j < 32; ++j) {
            ulonglong2 v = *(const ulonglong2*)(wp + 4 * j);
            w2[2 * j]     = v.x;
            w2[2 * j + 1] = v.y;
        }
    }

    // ---- init mbarrier ----
    if (tid == 0) {
        asm volatile("mbarrier.init.shared.b64 [%0], %1;" :: "r"(mbar_a), "r"(1) : "memory");
    }
    __syncthreads();

    for (int t = 0; t < TLEN; ++t) {
        // ---- prefetch ext[t+1] epilogue values (hidden behind barrier+compute) ----
        float e0 = 0.f, e1 = 0.f;
        if (t + 1 < TLEN) {
            const float* ebase = g_ext + (size_t)(t + 1) * (BATCH * D);
            e0 = __ldg(&ebase[(size_t)(Mb + rm0) * D + Nb + rn0]);
            e1 = __ldg(&ebase[(size_t)(Mb + rm1) * D + Nb + rn1]);
        }

        // ---- barrier: producers of g_sbuf[t&1] (step t-1) finished ----
        if (t > 0) {
            if (tid == 0) {
                const unsigned target = 32u * (unsigned)t;
                unsigned v;
                do {
                    asm volatile("ld.acquire.gpu.u32 %0, [%1];" : "=r"(v) : "l"(bar));
                } while (v < target);
            }
            __syncthreads();
        }

        // ---- one bulk copy: 64KB contiguous rows -> sTile ----
        if (tid == 0) {
            const float* src = (t == 0) ? (g_ext + (size_t)Mb * D)          // ext[0] slice (state0 = 0)
                                        : (g_sbuf[t & 1] + (size_t)Mb * D); // combined state+ext[t]
            asm volatile("mbarrier.arrive.expect_tx.shared.b64 _, [%0], %1;"
                         :: "r"(mbar_a), "r"(TILE_BYTES) : "memory");
            asm volatile("cp.async.bulk.shared::cta.global.mbarrier::complete_tx::bytes [%0], [%1], %2, [%3];"
                         :: "r"(sTile_a), "l"(src), "r"(TILE_BYTES), "r"(mbar_a) : "memory");
        }
        // all threads wait for the copy (phase parity = t&1)
        {
            const uint32_t parity = (uint32_t)(t & 1);
            uint32_t done;
            do {
                asm volatile(
                    "{\n\t.reg .pred p;\n\t"
                    "mbarrier.try_wait.parity.acquire.cta.shared::cta.b64 p, [%1], %2, 0x989680;\n\t"
                    "selp.b32 %0, 1, 0, p;\n\t}"
                    : "=r"(done) : "r"(mbar_a), "r"(parity) : "memory");
            } while (!done);
        }

        // ---- compute: acc[16 m] over this warp's 128-k slice (broadcast LDS) ----
        ULL acc[16];
#pragma unroll
        for (int i = 0; i < 16; ++i) acc[i] = 0ULL;

        const float* sb = sTile + w * 128;
#pragma unroll
        for (int m = 0; m < 16; ++m) {
            const ulonglong2* srow = (const ulonglong2*)(sb + (size_t)m * D);
#pragma unroll
            for (int j = 0; j < 32; ++j) {
                ulonglong2 sv = srow[j];
                fma2(acc[m], sv.x, w2[2 * j]);
                fma2(acc[m], sv.y, w2[2 * j + 1]);
            }
        }

        // ---- fold k-parity, write partials ----
#pragma unroll
        for (int m = 0; m < 16; ++m) {
            float lo, hi;
            unpack2(acc[m], lo, hi);
            red[w * 512 + m * 32 + l] = lo + hi;
        }
        __syncthreads();

        // ---- reduce 8 k-slices, ReLU, fuse ext[t+1], write combined buffer ----
        float* sout = g_sbuf[(t + 1) & 1];
        {
            float s0 = 0.f, s1 = 0.f;
#pragma unroll
            for (int g = 0; g < 8; g += 2) {
                s0 += red[g * 512 + tid];
                s1 += red[(g + 1) * 512 + tid];
            }
            float v = fmaxf(s0 + s1, 0.f);
            if (t + 1 < TLEN) v += e0;
            __stcg(&sout[(size_t)(Mb + rm0) * D + Nb + rn0], v);
        }
        {
            float s0 = 0.f, s1 = 0.f;
#pragma unroll
            for (int g = 0; g < 8; g += 2) {
                s0 += red[g * 512 + tid + 256];
                s1 += red[(g + 1) * 512 + tid + 256];
            }
            float v = fmaxf(s0 + s1, 0.f);
            if (t + 1 < TLEN) v += e1;
            __stcg(&sout[(size_t)(Mb + rm1) * D + Nb + rn1], v);
        }
        __syncthreads();   // all writes done; sTile free for next bulk

        if (tid == 0) {
            __threadfence();
            atomicAdd(bar, 1u);
        }
    }
}

// ---------------- final: out[:,0,:] = final state (in g_sbuf[0], t=512 even) --------
__global__ void final_copy_kernel(float* __restrict__ out) {
    const int i = blockIdx.x * blockDim.x + threadIdx.x;   // < 65536
    const int b = i >> 10, o = i & 1023;
    out[(size_t)b * (TLEN * D) + o] = g_sbuf[0][i];
}

// ---------------- launch ----------------
extern "C" void kernel_launch(void* const* d_in, const int* in_sizes, int n_in,
                              void* d_out, int out_size) {
    const float* x     = (const float*)d_in[0];
    const float* W_in  = (const float*)d_in[1];
    const float* W_rec = (const float*)d_in[2];
    float* out = (float*)d_out;

    cudaFuncSetAttribute(rnn_persistent, cudaFuncAttributeMaxDynamicSharedMemorySize, PERS_SMEM);
    cudaFuncSetAttribute(ext_gemm_kernel, cudaFuncAttributeMaxDynamicSharedMemorySize, EXT_SMEM);

    // zero output (poisoned by harness) + barrier counters
    zero4_kernel<<<(BATCH * TLEN * D / 4 + 255) / 256, 256>>>((float4*)out, BATCH * TLEN * D / 4);
    zero_misc_kernel<<<1, 128>>>();

    // Phase A: input projections for all timesteps (ext layout [t][b][o])
    ext_gemm_kernel<<<dim3(D / BN, (BATCH * TLEN) / BM), 256, EXT_SMEM>>>(x, W_in);

    // Phase B: full recurrence in one persistent kernel
    rnn_persistent<<<dim3(D / NTILE, BATCH / MTILE), 256, PERS_SMEM>>>(W_rec);

    // write final state into out[:,0,:]
    final_copy_kernel<<<(BATCH * D) / 256, 256>>>(out);
}

// round 12
// speedup vs baseline: 1.1437x; 1.0438x over previous
#include <cuda_runtime.h>
#include <cstdint>

#define BATCH 64
#define TLEN  512
#define D     1024

// ---------------- scratch (device globals: no allocations allowed) ----------------
__device__ float g_ext[(size_t)TLEN * BATCH * D];   // 128 MB, layout [t][b][o]
__device__ float g_sbuf[2][BATCH * D];              // ping-pong: state + ext[t] combined
__device__ unsigned g_bars[4 * 32];                  // per-m-group barrier counters

typedef unsigned long long ULL;

// ---------------- packed f32x2 helpers (sm_103a FFMA2 path) ----------------
static __device__ __forceinline__ ULL pack_dup(float w) {
    ULL r;
    asm("mov.b64 %0, {%1, %1};" : "=l"(r) : "f"(w));
    return r;
}
static __device__ __forceinline__ void fma2(ULL& d, ULL a, ULL b) {
    asm("fma.rn.f32x2 %0, %1, %2, %0;" : "+l"(d) : "l"(a), "l"(b));
}
static __device__ __forceinline__ void unpack2(ULL v, float& lo, float& hi) {
    asm("mov.b64 {%0, %1}, %2;" : "=f"(lo), "=f"(hi) : "l"(v));
}
static __device__ __forceinline__ uint32_t smem_u32(const void* p) {
    uint32_t a;
    asm("{ .reg .u64 t; cvta.to.shared.u64 t, %1; cvt.u32.u64 %0, t; }" : "=r"(a) : "l"(p));
    return a;
}

// ---------------- trivial zero kernels ----------------
__global__ void zero4_kernel(float4* __restrict__ p, int n4) {
    int i = blockIdx.x * blockDim.x + threadIdx.x;
    if (i < n4) p[i] = make_float4(0.f, 0.f, 0.f, 0.f);
}
__global__ void zero_misc_kernel() {
    int i = blockIdx.x * blockDim.x + threadIdx.x;
    if (i < 4 * 32) g_bars[i] = 0u;
}

// ---------------- Phase A: ext[t][b][o] = sum_k x[m][k] * W_in[o][k], m=b*512+t --------
#define BM 128
#define BN 64
#define BK 32
#define PADA 134
#define PADB 68
#define ASTRIDE (BK * PADA)
#define BSTRIDE (BK * PADB)
#define EXT_SMEM ((2 * ASTRIDE + 2 * BSTRIDE) * 4)   // 51712 B

__global__ __launch_bounds__(256, 2) void ext_gemm_kernel(const float* __restrict__ X,
                                                          const float* __restrict__ Win) {
    extern __shared__ float esm[];
    float* As = esm;
    float* Bs = esm + 2 * ASTRIDE;

    const int tid = threadIdx.x;
    const int Mb = blockIdx.y * BM;
    const int Nb = blockIdx.x * BN;
    const int ty = tid >> 4, tx = tid & 15;
    const int m0 = ty * 8, n0 = tx * 4;

    ULL acc[4][4];
#pragma unroll
    for (int i = 0; i < 4; ++i)
#pragma unroll
        for (int j = 0; j < 4; ++j) acc[i][j] = 0ULL;

    const int ar = tid >> 3, ac = tid & 7;
    const int br = tid >> 2, bc = tid & 3;

    float4 ra[4], rb[2];
#pragma unroll
    for (int g = 0; g < 4; ++g)
        ra[g] = *(const float4*)&X[(size_t)(Mb + ar + g * 32) * D + ac * 4];
#pragma unroll
    for (int g = 0; g < 2; ++g)
        rb[g] = *(const float4*)&Win[(size_t)(Nb + br) * D + (bc + g * 4) * 4];
    {
#pragma unroll
        for (int g = 0; g < 4; ++g) {
            const int m = ar + g * 32;
            As[(ac * 4 + 0) * PADA + m] = ra[g].x;
            As[(ac * 4 + 1) * PADA + m] = ra[g].y;
            As[(ac * 4 + 2) * PADA + m] = ra[g].z;
            As[(ac * 4 + 3) * PADA + m] = ra[g].w;
        }
#pragma unroll
        for (int g = 0; g < 2; ++g) {
            const int cc = bc + g * 4;
            Bs[(cc * 4 + 0) * PADB + br] = rb[g].x;
            Bs[(cc * 4 + 1) * PADB + br] = rb[g].y;
            Bs[(cc * 4 + 2) * PADB + br] = rb[g].z;
            Bs[(cc * 4 + 3) * PADB + br] = rb[g].w;
        }
    }
    __syncthreads();

    for (int kt = 0; kt < D / BK; ++kt) {
        const int s = kt & 1;
        const float* Ac = As + s * ASTRIDE;
        const float* Bc = Bs + s * BSTRIDE;

        if (kt < D / BK - 1) {
            const int k0 = (kt + 1) * BK;
#pragma unroll
            for (int g = 0; g < 4; ++g)
                ra[g] = *(const float4*)&X[(size_t)(Mb + ar + g * 32) * D + k0 + ac * 4];
#pragma unroll
            for (int g = 0; g < 2; ++g)
                rb[g] = *(const float4*)&Win[(size_t)(Nb + br) * D + k0 + (bc + g * 4) * 4];
        }

#pragma unroll
        for (int kk = 0; kk < BK; ++kk) {
            const float* asr = &Ac[kk * PADA + m0];
            ULL a0 = *(const ULL*)(asr + 0);
            ULL a1 = *(const ULL*)(asr + 2);
            ULL a2 = *(const ULL*)(asr + 4);
            ULL a3 = *(const ULL*)(asr + 6);
            float4 bv = *(const float4*)&Bc[kk * PADB + n0];
            ULL b0 = pack_dup(bv.x);
            ULL b1 = pack_dup(bv.y);
            ULL b2 = pack_dup(bv.z);
            ULL b3 = pack_dup(bv.w);
            fma2(acc[0][0], a0, b0); fma2(acc[0][1], a0, b1); fma2(acc[0][2], a0, b2); fma2(acc[0][3], a0, b3);
            fma2(acc[1][0], a1, b0); fma2(acc[1][1], a1, b1); fma2(acc[1][2], a1, b2); fma2(acc[1][3], a1, b3);
            fma2(acc[2][0], a2, b0); fma2(acc[2][1], a2, b1); fma2(acc[2][2], a2, b2); fma2(acc[2][3], a2, b3);
            fma2(acc[3][0], a3, b0); fma2(acc[3][1], a3, b1); fma2(acc[3][2], a3, b2); fma2(acc[3][3], a3, b3);
        }

        if (kt < D / BK - 1) {
            float* An = As + (s ^ 1) * ASTRIDE;
            float* Bn = Bs + (s ^ 1) * BSTRIDE;
#pragma unroll
            for (int g = 0; g < 4; ++g) {
                const int m = ar + g * 32;
                An[(ac * 4 + 0) * PADA + m] = ra[g].x;
                An[(ac * 4 + 1) * PADA + m] = ra[g].y;
                An[(ac * 4 + 2) * PADA + m] = ra[g].z;
                An[(ac * 4 + 3) * PADA + m] = ra[g].w;
            }
#pragma unroll
            for (int g = 0; g < 2; ++g) {
                const int cc = bc + g * 4;
                Bn[(cc * 4 + 0) * PADB + br] = rb[g].x;
                Bn[(cc * 4 + 1) * PADB + br] = rb[g].y;
                Bn[(cc * 4 + 2) * PADB + br] = rb[g].z;
                Bn[(cc * 4 + 3) * PADB + br] = rb[g].w;
            }
        }
        __syncthreads();
    }

#pragma unroll
    for (int i = 0; i < 4; ++i) {
        float lo[4], hi[4];
#pragma unroll
        for (int j = 0; j < 4; ++j) unpack2(acc[i][j], lo[j], hi[j]);
        const int m = Mb + m0 + 2 * i;
        const int b0i = m >> 9, t0i = m & 511;
        const int b1i = (m + 1) >> 9, t1i = (m + 1) & 511;
        *(float4*)&g_ext[((size_t)t0i * BATCH + b0i) * D + Nb + n0] = make_float4(lo[0], lo[1], lo[2], lo[3]);
        *(float4*)&g_ext[((size_t)t1i * BATCH + b1i) * D + Nb + n0] = make_float4(hi[0], hi[1], hi[2], hi[3]);
    }
}

// ---------------- Phase B: persistent recurrence, crossbar-balanced ----------------
// 256 threads, 8 warps. Warp w owns k-slice [w*128, +128). Lane = (mg 0..7, ng 0..3):
// computes m in {mg, mg+8} x n in [8*ng, 8*ng+8) -> acc = 2m x 4 n-pairs = 8 ULL.
// W transposed in smem WT[k][n] (stride 36: conflict-free LDS.128); s-tile row-major
// stride 1028 (bank shift 4 -> conflict-free a-LDS.64). All LDS have distinct lane
// addresses -> ~3072 crossbar phases vs 4096 FMA cycles per step: FMA-bound.
// Staging: 32 cp.async.bulk (2KB each) split into k-halves with 2 mbarriers so
// warps 0-3 start on half 0 while half 1 is in flight. Epilogue fuses relu+ext[t+1].
#define NTILE 32
#define MTILE 16
#define WT_STRIDE 36
#define WT_FLOATS (D * WT_STRIDE)            // 36864
#define ST_STRIDE 1028
#define ST_FLOATS (MTILE * ST_STRIDE)        // 16448
#define RED_WSTR 544                         // 16 m * 34
#define RED_FLOATS (8 * RED_WSTR)            // 4352
#define OFF_MBAR ((WT_FLOATS + ST_FLOATS + RED_FLOATS) * 4)
#define PERS_SMEM (OFF_MBAR + 32)            // 230688 B

__global__ __launch_bounds__(256, 1) void rnn_persistent(const float* __restrict__ Wr) {
    extern __shared__ float sm[];
    float* WT  = sm;                          // [1024 k][36]
    float* sT  = sm + WT_FLOATS;              // [16 m][1028]
    float* red = sm + WT_FLOATS + ST_FLOATS;  // [8 w][16 m * 34]

    const int tid  = threadIdx.x;
    const int w    = tid >> 5;
    const int lane = tid & 31;
    const int mg   = lane & 7;
    const int ng   = lane >> 3;
    const int n0   = ng * 8;
    const int kbase = w * 128;
    const int Nb = blockIdx.x * NTILE;
    const int Mb = blockIdx.y * MTILE;
    unsigned* bar = &g_bars[blockIdx.y * 32];

    const uint32_t mbarA = smem_u32(sm) + OFF_MBAR;
    const uint32_t mbarB = mbarA + 8;
    const uint32_t sT_a  = smem_u32(sT);

    // epilogue/reduce mapping
    const int em = tid >> 4;        // m row 0..15
    const int enp = tid & 15;       // n-pair 0..15

    // ---- stage WT[k][n] (transposed W slice; once for all steps) ----
    {
        const int n = tid & 31, kc = tid >> 5;      // kc 0..7 -> k chunk of 128
        const float* wp = Wr + (size_t)(Nb + n) * D + kc * 128;
        float* wt = WT + (size_t)(kc * 128) * WT_STRIDE + n;
#pragma unroll
        for (int j = 0; j < 32; ++j) {
            float4 v = __ldg((const float4*)(wp + 4 * j));
            float* dst = wt + (4 * j) * WT_STRIDE;
            dst[0] = v.x;
            dst[WT_STRIDE] = v.y;
            dst[2 * WT_STRIDE] = v.z;
            dst[3 * WT_STRIDE] = v.w;
        }
    }
    if (tid == 0) {
        asm volatile("mbarrier.init.shared.b64 [%0], %1;" :: "r"(mbarA), "r"(1) : "memory");
        asm volatile("mbarrier.init.shared.b64 [%0], %1;" :: "r"(mbarB), "r"(1) : "memory");
    }
    __syncthreads();

    for (int t = 0; t < TLEN; ++t) {
        // ---- prefetch ext[t+1] epilogue pair (hidden behind barrier+compute) ----
        float2 e = make_float2(0.f, 0.f);
        if (t + 1 < TLEN) {
            const float* eb = g_ext + (size_t)(t + 1) * (BATCH * D) + (size_t)(Mb + em) * D + Nb + 2 * enp;
            e = __ldg((const float2*)eb);
        }

        // ---- barrier: producers of g_sbuf[t&1] finished step t-1 ----
        if (t > 0) {
            if (tid == 0) {
                const unsigned target = 32u * (unsigned)t;
                unsigned v;
                do {
                    asm volatile("ld.acquire.gpu.u32 %0, [%1];" : "=r"(v) : "l"(bar));
                } while (v < target);
            }
            __syncthreads();
        }

        // ---- bulk copies: 16 rows x 2 k-halves (2KB each), 2 mbarriers ----
        if (tid == 0) {
            const float* src = (t == 0) ? (g_ext + (size_t)Mb * D)
                                        : (g_sbuf[t & 1] + (size_t)Mb * D);
            asm volatile("mbarrier.arrive.expect_tx.shared.b64 _, [%0], %1;"
                         :: "r"(mbarA), "r"(32768) : "memory");
            asm volatile("mbarrier.arrive.expect_tx.shared.b64 _, [%0], %1;"
                         :: "r"(mbarB), "r"(32768) : "memory");
#pragma unroll
            for (int m = 0; m < MTILE; ++m) {
                const float* s0 = src + (size_t)m * D;
                uint32_t d0 = sT_a + (uint32_t)(m * ST_STRIDE) * 4u;
                asm volatile("cp.async.bulk.shared::cta.global.mbarrier::complete_tx::bytes [%0], [%1], %2, [%3];"
                             :: "r"(d0), "l"(s0), "r"(2048), "r"(mbarA) : "memory");
                asm volatile("cp.async.bulk.shared::cta.global.mbarrier::complete_tx::bytes [%0], [%1], %2, [%3];"
                             :: "r"(d0 + 2048u), "l"(s0 + 512), "r"(2048), "r"(mbarB) : "memory");
            }
        }
        // wait for this warp's k-half
        {
            const uint32_t mb = (w < 4) ? mbarA : mbarB;
            const uint32_t parity = (uint32_t)(t & 1);
            uint32_t done;
            do {
                asm volatile(
                    "{\n\t.reg .pred p;\n\t"
                    "mbarrier.try_wait.parity.acquire.cta.shared::cta.b64 p, [%1], %2, 0x989680;\n\t"
                    "selp.b32 %0, 1, 0, p;\n\t}"
                    : "=r"(done) : "r"(mb), "r"(parity) : "memory");
            } while (!done);
        }

        // ---- compute: 2m x 8n per lane over this warp's 128-k slice ----
        ULL acc[8];
#pragma unroll
        for (int i = 0; i < 8; ++i) acc[i] = 0ULL;

        const float* a0p = sT + (size_t)mg * ST_STRIDE + kbase;
        const float* a1p = sT + (size_t)(mg + 8) * ST_STRIDE + kbase;
        const float* wtp = WT + (size_t)kbase * WT_STRIDE + n0;

#pragma unroll 8
        for (int i = 0; i < 64; ++i) {
            const int k2 = 2 * i;
            float2 av0 = *(const float2*)(a0p + k2);
            float2 av1 = *(const float2*)(a1p + k2);
            const float* wk = wtp + k2 * WT_STRIDE;
            ulonglong2 w0a = *(const ulonglong2*)(wk);
            ulonglong2 w0b = *(const ulonglong2*)(wk + 4);
            ulonglong2 w1a = *(const ulonglong2*)(wk + WT_STRIDE);
            ulonglong2 w1b = *(const ulonglong2*)(wk + WT_STRIDE + 4);
            ULL a00 = pack_dup(av0.x), a10 = pack_dup(av1.x);
            fma2(acc[0], a00, w0a.x); fma2(acc[1], a00, w0a.y);
            fma2(acc[2], a00, w0b.x); fma2(acc[3], a00, w0b.y);
            fma2(acc[4], a10, w0a.x); fma2(acc[5], a10, w0a.y);
            fma2(acc[6], a10, w0b.x); fma2(acc[7], a10, w0b.y);
            ULL a01 = pack_dup(av0.y), a11 = pack_dup(av1.y);
            fma2(acc[0], a01, w1a.x); fma2(acc[1], a01, w1a.y);
            fma2(acc[2], a01, w1b.x); fma2(acc[3], a01, w1b.y);
            fma2(acc[4], a11, w1a.x); fma2(acc[5], a11, w1a.y);
            fma2(acc[6], a11, w1b.x); fma2(acc[7], a11, w1b.y);
        }

        // ---- store per-warp partials (n-pair packed ULL stores) ----
        {
            float* rw = red + w * RED_WSTR;
#pragma unroll
            for (int p = 0; p < 4; ++p) {
                *(ULL*)(rw + mg * 34 + n0 + 2 * p)       = acc[p];
                *(ULL*)(rw + (mg + 8) * 34 + n0 + 2 * p) = acc[4 + p];
            }
        }
        __syncthreads();

        // ---- reduce over 8 warps, ReLU, fuse ext[t+1], write combined buffer ----
        {
            const float* rp = red + em * 34 + 2 * enp;
            float s0 = 0.f, s1 = 0.f;
#pragma unroll
            for (int g = 0; g < 8; ++g) {
                float2 v = *(const float2*)(rp + g * RED_WSTR);
                s0 += v.x; s1 += v.y;
            }
            float v0 = fmaxf(s0, 0.f);
            float v1 = fmaxf(s1, 0.f);
            if (t + 1 < TLEN) { v0 += e.x; v1 += e.y; }
            float* sout = g_sbuf[(t + 1) & 1];
            float2 o = make_float2(v0, v1);
            __stcg((float2*)&sout[(size_t)(Mb + em) * D + Nb + 2 * enp], o);
        }
        __syncthreads();   // all reads of red / sT done before next overwrite

        if (tid == 0) {
            __threadfence();
            atomicAdd(bar, 1u);
        }
    }
}

// ---------------- final: out[:,0,:] = final state (g_sbuf[0], TLEN even) ----------------
__global__ void final_copy_kernel(float* __restrict__ out) {
    const int i = blockIdx.x * blockDim.x + threadIdx.x;   // < 65536
    const int b = i >> 10, o = i & 1023;
    out[(size_t)b * (TLEN * D) + o] = g_sbuf[0][i];
}

// ---------------- launch ----------------
extern "C" void kernel_launch(void* const* d_in, const int* in_sizes, int n_in,
                              void* d_out, int out_size) {
    const float* x     = (const float*)d_in[0];
    const float* W_in  = (const float*)d_in[1];
    const float* W_rec = (const float*)d_in[2];
    float* out = (float*)d_out;

    cudaFuncSetAttribute(rnn_persistent, cudaFuncAttributeMaxDynamicSharedMemorySize, PERS_SMEM);
    cudaFuncSetAttribute(ext_gemm_kernel, cudaFuncAttributeMaxDynamicSharedMemorySize, EXT_SMEM);

    // zero output (poisoned by harness) + barrier counters
    zero4_kernel<<<(BATCH * TLEN * D / 4 + 255) / 256, 256>>>((float4*)out, BATCH * TLEN * D / 4);
    zero_misc_kernel<<<1, 128>>>();

    // Phase A: input projections for all timesteps (ext layout [t][b][o])
    ext_gemm_kernel<<<dim3(D / BN, (BATCH * TLEN) / BM), 256, EXT_SMEM>>>(x, W_in);

    // Phase B: full recurrence in one persistent kernel
    rnn_persistent<<<dim3(D / NTILE, BATCH / MTILE), 256, PERS_SMEM>>>(W_rec);

    // write final state into out[:,0,:]
    final_copy_kernel<<<(BATCH * D) / 256, 256>>>(out);
}